// round 15
// baseline (speedup 1.0000x reference)
#include <cuda_runtime.h>
#include <cstdint>

#define BATCH 65536
#define NP 2048
#define RPB 16                     /* rows per block = pipeline steps */
#define NBLK (BATCH / RPB)         /* 4096 */
#define NT 256
#define NSLOT 4                    /* smem ring slots (1 row each) */
#define DEPTH 3                    /* TMA stages in flight */
#define ROW_BYTES (NP * 4)         /* 8192 */
#define INV_SQRT2F 0.70710678118654752440f

// Per-block partial sums: [blk*8 + comp]
// 0..3 : SumA, SumBr, SumBi, SumC    4..7 : sum(c_r), sum(c_r^2), sum(c_i), sum(c_i^2)
__device__ float g_partials[NBLK * 8];
__device__ int   g_count = 0;

__device__ __forceinline__ void mbar_init(unsigned a, unsigned cnt) {
    asm volatile("mbarrier.init.shared.b64 [%0], %1;" :: "r"(a), "r"(cnt) : "memory");
}
__device__ __forceinline__ void mbar_expect_tx(unsigned a, unsigned bytes) {
    asm volatile("mbarrier.arrive.expect_tx.shared.b64 _, [%0], %1;"
                 :: "r"(a), "r"(bytes) : "memory");
}
__device__ __forceinline__ void mbar_wait(unsigned a, unsigned phase) {
    asm volatile(
        "{\n\t"
        ".reg .pred P;\n"
        "W_%=:\n\t"
        "mbarrier.try_wait.parity.acquire.cta.shared::cta.b64 P, [%0], %1, 0x989680;\n\t"
        "@P bra D_%=;\n\t"
        "bra W_%=;\n"
        "D_%=:\n\t"
        "}"
        :: "r"(a), "r"(phase) : "memory");
}
__device__ __forceinline__ void tma_bulk_1d(unsigned dst, const void* src,
                                            unsigned bytes, unsigned mbar) {
    asm volatile(
        "cp.async.bulk.shared::cta.global.mbarrier::complete_tx::bytes "
        "[%0], [%1], %2, [%3];"
        :: "r"(dst), "l"(src), "r"(bytes), "r"(mbar) : "memory");
}

__global__ __launch_bounds__(NT, 6) void isi_fused_kernel(
    const float* __restrict__ dnn,
    const float* __restrict__ bv,
    const float* __restrict__ hv,
    const float* __restrict__ xr,
    const float* __restrict__ xi,
    const float* __restrict__ isr,   // ISI_symbols_real (B,6)
    const float* __restrict__ isi,   // ISI_symbols_imag (B,6)
    const float* __restrict__ ich,   // ISI_channels     (B,6)
    const float* __restrict__ noise,
    const float* __restrict__ prob,
    float* __restrict__ out)
{
    // Ring: 4 slots x 1 row x 8KB = 32 KB. Final-combine double scratch
    // (16 KB) overlays the ring after the main loop (fenced by barriers).
    __shared__ __align__(16) char smem_raw[NSLOT * ROW_BYTES];
    float* ring = (float*)smem_raw;
    __shared__ __align__(8) unsigned long long mbar[NSLOT];
    __shared__ float scoef[RPB * 5];         // bb, ar_c, ai_c, br_c, bi_c per row
    __shared__ float sred[8 * 8];

    const int tid  = threadIdx.x;
    const int blk  = blockIdx.x;
    const int row0 = blk * RPB;
    const int t    = (tid < 146) ? tid : 145;   // clamped float2 j-slot

    float sA = 0.f, sBr = 0.f, sBi = 0.f, sC = 0.f;
    float sM1r = 0.f, sM2r = 0.f, sM1i = 0.f, sM2i = 0.f;

    // prob float2 for j = 2t, 2t+1 (cols 878+2t, 879+2t); zero inactive lanes.
    float2 p2 = ((const float2*)prob)[439 + t];
    if (tid >= 146) { p2.x = 0.f; p2.y = 0.f; }

    // Per-row coefficients + moment terms (threads 0..RPB-1)
    if (tid < RPB) {
        const int r = row0 + tid;
        const float bb  = bv[r];
        const float bh  = bb * hv[r];
        const float xrr = xr[r];
        const float xii = xi[r];
        const float nz  = INV_SQRT2F * noise[r];
        scoef[tid * 5 + 0] = bb;
        scoef[tid * 5 + 1] = bh * xrr;
        scoef[tid * 5 + 2] = bh * xii;
        scoef[tid * 5 + 3] = nz - xrr;
        scoef[tid * 5 + 4] = nz - xii;

        const float c  = ich[(size_t)r * 6];
        const float cr = c * isr[(size_t)r * 6];
        const float ci = c * isi[(size_t)r * 6];
        sM1r = cr; sM2r = cr * cr;
        sM1i = ci; sM2i = ci * ci;
    }

    const unsigned ring_base = (unsigned)__cvta_generic_to_shared(ring);
    const unsigned mbar_base = (unsigned)__cvta_generic_to_shared(mbar);

    if (tid == 0) {
        #pragma unroll
        for (int i = 0; i < NSLOT; ++i) mbar_init(mbar_base + 8u * i, 1);
    }
    __syncthreads();   // mbarriers + scoef visible

    // Prologue: launch DEPTH stages
    if (tid == 0) {
        #pragma unroll
        for (int k = 0; k < DEPTH; ++k) {
            const unsigned mb = mbar_base + 8u * (k & (NSLOT - 1));
            mbar_expect_tx(mb, ROW_BYTES);
            tma_bulk_1d(ring_base + (unsigned)(k & (NSLOT - 1)) * ROW_BYTES,
                        dnn + (size_t)(row0 + k) * NP, ROW_BYTES, mb);
        }
    }

    #pragma unroll
    for (int st = 0; st < RPB; ++st) {
        const int slot = st & (NSLOT - 1);
        mbar_wait(mbar_base + 8u * slot, (st >> 2) & 1);

        // compute row st from ring slot
        {
            const float2* rp = (const float2*)(ring + slot * NP);
            float2 s0 = rp[  1 + t];
            float2 s1 = rp[147 + t];
            float2 s2 = rp[293 + t];
            float2 d0 = rp[439 + t];
            float2 s3 = rp[585 + t];
            float2 s4 = rp[731 + t];
            float2 s5 = rp[877 + t];
            const float bb  = scoef[st * 5 + 0];
            const float arc = scoef[st * 5 + 1];
            const float aic = scoef[st * 5 + 2];
            const float brc = scoef[st * 5 + 3];
            const float bic = scoef[st * 5 + 4];
            {   // lane 0
                float S  = s0.x + s1.x + s2.x + s3.x + s4.x + s5.x;
                float ar = fmaf(arc, d0.x, brc);
                float ai = fmaf(aic, d0.x, bic);
                float bS = bb * S;
                sA  = fmaf(p2.x, fmaf(ar, ar, ai * ai), sA);
                sBr = fmaf(p2.x, ar * bS, sBr);
                sBi = fmaf(p2.x, ai * bS, sBi);
                sC  = fmaf(p2.x, bS * bS, sC);
            }
            {   // lane 1
                float S  = s0.y + s1.y + s2.y + s3.y + s4.y + s5.y;
                float ar = fmaf(arc, d0.y, brc);
                float ai = fmaf(aic, d0.y, bic);
                float bS = bb * S;
                sA  = fmaf(p2.y, fmaf(ar, ar, ai * ai), sA);
                sBr = fmaf(p2.y, ar * bS, sBr);
                sBi = fmaf(p2.y, ai * bS, sBi);
                sC  = fmaf(p2.y, bS * bS, sC);
            }
        }

        __syncthreads();   // all reads of `slot` done; prior step's reads of
                           // slot (st-1)&3 are also fenced -> safe to refill it
        if (tid == 0 && st + DEPTH < RPB) {
            const int k  = st + DEPTH;
            const unsigned mb = mbar_base + 8u * (k & (NSLOT - 1));
            mbar_expect_tx(mb, ROW_BYTES);
            tma_bulk_1d(ring_base + (unsigned)(k & (NSLOT - 1)) * ROW_BYTES,
                        dnn + (size_t)(row0 + k) * NP, ROW_BYTES, mb);
        }
    }

    // Block reduction: warp shuffle then across 8 warps via smem
    const unsigned FULL = 0xFFFFFFFFu;
    #pragma unroll
    for (int o = 16; o > 0; o >>= 1) {
        sA   += __shfl_down_sync(FULL, sA, o);
        sBr  += __shfl_down_sync(FULL, sBr, o);
        sBi  += __shfl_down_sync(FULL, sBi, o);
        sC   += __shfl_down_sync(FULL, sC, o);
        sM1r += __shfl_down_sync(FULL, sM1r, o);
        sM2r += __shfl_down_sync(FULL, sM2r, o);
        sM1i += __shfl_down_sync(FULL, sM1i, o);
        sM2i += __shfl_down_sync(FULL, sM2i, o);
    }
    const int warp = tid >> 5, lane = tid & 31;
    if (lane == 0) {
        sred[warp * 8 + 0] = sA;   sred[warp * 8 + 1] = sBr;
        sred[warp * 8 + 2] = sBi;  sred[warp * 8 + 3] = sC;
        sred[warp * 8 + 4] = sM1r; sred[warp * 8 + 5] = sM2r;
        sred[warp * 8 + 6] = sM1i; sred[warp * 8 + 7] = sM2i;
    }
    __syncthreads();
    if (tid < 8) {
        float acc = 0.f;
        #pragma unroll
        for (int w = 0; w < 8; ++w) acc += sred[w * 8 + tid];
        g_partials[blk * 8 + tid] = acc;
    }

    // ---- last-block final combine (deterministic: fixed summation order) ----
    __shared__ int s_last;
    __threadfence();
    __syncthreads();
    if (tid == 0)
        s_last = (atomicAdd(&g_count, 1) == NBLK - 1);
    __syncthreads();
    if (!s_last) return;

    __threadfence();  // acquire: all blocks' partials visible

    double* dsm = (double*)smem_raw;          // overlay: 8*256*8 = 16 KB < 32 KB
    double acc[8];
    #pragma unroll
    for (int c = 0; c < 8; ++c) acc[c] = 0.0;
    for (int b = tid; b < NBLK; b += NT) {
        #pragma unroll
        for (int c = 0; c < 8; ++c)
            acc[c] += (double)g_partials[b * 8 + c];
    }
    #pragma unroll
    for (int c = 0; c < 8; ++c) dsm[c * NT + tid] = acc[c];
    __syncthreads();

    if (tid < 8) {
        double sum = 0.0;
        for (int i = 0; i < NT; ++i) sum += dsm[tid * NT + i];
        dsm[tid] = sum;
    }
    __syncthreads();
    if (tid == 0) {
        const double invB = 1.0 / (double)BATCH;
        double SumA  = dsm[0], SumBr = dsm[1], SumBi = dsm[2], SumC = dsm[3];
        double m1r = dsm[4] * invB, m2r = dsm[5] * invB;
        double m1i = dsm[6] * invB, m2i = dsm[7] * invB;
        out[0] = (float)((SumA + 2.0 * m1r * SumBr + 2.0 * m1i * SumBi
                          + (m2r + m2i) * SumC) * invB);
        g_count = 0;   // self-reset for next graph replay
    }
}

extern "C" void kernel_launch(void* const* d_in, const int* in_sizes, int n_in,
                              void* d_out, int out_size)
{
    const float* dnn   = (const float*)d_in[0];
    const float* bv    = (const float*)d_in[1];
    const float* hv    = (const float*)d_in[2];
    const float* xr    = (const float*)d_in[3];
    const float* xi    = (const float*)d_in[4];
    const float* isr   = (const float*)d_in[5];
    const float* isi   = (const float*)d_in[6];
    const float* ich   = (const float*)d_in[7];
    const float* noise = (const float*)d_in[8];
    const float* prob  = (const float*)d_in[9];

    isi_fused_kernel<<<NBLK, NT>>>(dnn, bv, hv, xr, xi, isr, isi, ich,
                                   noise, prob, (float*)d_out);
}

// round 16
// speedup vs baseline: 1.1963x; 1.1963x over previous
#include <cuda_runtime.h>
#include <cstdint>

#define BATCH 65536
#define NP 2048
#define RPB 8                      /* rows per block */
#define NBLK (BATCH / RPB)         /* 8192 */
#define GRPSZ 64                   /* blocks per combine group */
#define NGRP (NBLK / GRPSZ)        /* 128 */
#define NT 160                     /* 2 groups of 80 threads; 74 active each */
#define INV_SQRT2F 0.70710678118654752440f

// Per-block partial sums: [blk*8 + comp]
// 0..3 : SumA, SumBr, SumBi, SumC    4..7 : sum(c_r), sum(c_r^2), sum(c_i), sum(c_i^2)
__device__ float  g_partials[NBLK * 8];
__device__ double g_super[NGRP * 8];
__device__ int    g_grp_count[NGRP];
__device__ int    g_count = 0;

// Stream offsets in float4 units within a row (cols {2,294,586,878,1170,1462,1754}+j,
// j = 4t-2+e  ->  float4 index = {0,73,146,219,292,365,438} + t). Stream 3 is d0.
#define LOAD7(P, rp)                                   \
    {                                                  \
        P##0 = (rp)[0];    P##1 = (rp)[73];            \
        P##2 = (rp)[146];  P##3 = (rp)[219];           \
        P##4 = (rp)[292];  P##5 = (rp)[365];           \
        P##6 = (rp)[438];                              \
    }

#define LANE(P, e, pw)                                                   \
    {                                                                    \
        float S  = (P##0).e + (P##1).e + (P##2).e                        \
                 + (P##4).e + (P##5).e + (P##6).e;                       \
        float ar = fmaf(arc, (P##3).e, brc);                             \
        float ai = fmaf(aic, (P##3).e, bic);                             \
        float bS = bb * S;                                               \
        sA  = fmaf(pw, fmaf(ar, ar, ai * ai), sA);                       \
        sBr = fmaf(pw, ar * bS, sBr);                                    \
        sBi = fmaf(pw, ai * bS, sBi);                                    \
        sC  = fmaf(pw, bS * bS, sC);                                     \
    }

#define COMPUTE7(P, ridx)                                           \
    {                                                               \
        const float bb  = scoef[(ridx) * 5 + 0];                    \
        const float arc = scoef[(ridx) * 5 + 1];                    \
        const float aic = scoef[(ridx) * 5 + 2];                    \
        const float brc = scoef[(ridx) * 5 + 3];                    \
        const float bic = scoef[(ridx) * 5 + 4];                    \
        LANE(P, x, p4.x) LANE(P, y, p4.y)                           \
        LANE(P, z, p4.z) LANE(P, w, p4.w)                           \
    }

__global__ __launch_bounds__(NT, 4) void isi_fused_kernel(
    const float* __restrict__ dnn,
    const float* __restrict__ bv,
    const float* __restrict__ hv,
    const float* __restrict__ xr,
    const float* __restrict__ xi,
    const float* __restrict__ isr,   // ISI_symbols_real (B,6)
    const float* __restrict__ isi,   // ISI_symbols_imag (B,6)
    const float* __restrict__ ich,   // ISI_channels     (B,6)
    const float* __restrict__ noise,
    const float* __restrict__ prob,
    float* __restrict__ out)
{
    const int tid  = threadIdx.x;
    const int blk  = blockIdx.x;
    const int grp  = blk >> 6;              // combine group (64 blocks)
    const int row0 = blk * RPB;
    const int g    = tid / 80;              // row-group 0/1
    const int s    = tid % 80;              // slot within group
    const int t    = (s < 74) ? s : 73;     // clamped j-slot (always in-bounds)

    __shared__ float scoef[RPB * 5];        // bb, ar_c, ai_c, br_c, bi_c per row

    float sA = 0.f, sBr = 0.f, sBi = 0.f, sC = 0.f;
    float sM1r = 0.f, sM2r = 0.f, sM1i = 0.f, sM2i = 0.f;

    // prob float4: cols 876+4t .. 879+4t  == p[878 + j], j = 4t-2+e.
    // Zero invalid lanes (edge j outside [0,292)) and inactive threads.
    float4 p4 = __ldg((const float4*)prob + 219 + t);
    if (s >= 74) { p4.x = 0.f; p4.y = 0.f; p4.z = 0.f; p4.w = 0.f; }
    if (t == 0)  { p4.x = 0.f; p4.y = 0.f; }
    if (t == 73) { p4.z = 0.f; p4.w = 0.f; }

    // Per-row coefficients + moment terms (threads 0..RPB-1)
    if (tid < RPB) {
        const int r = row0 + tid;
        const float bb  = bv[r];
        const float bh  = bb * hv[r];
        const float xrr = xr[r];
        const float xii = xi[r];
        const float nz  = INV_SQRT2F * noise[r];
        scoef[tid * 5 + 0] = bb;
        scoef[tid * 5 + 1] = bh * xrr;
        scoef[tid * 5 + 2] = bh * xii;
        scoef[tid * 5 + 3] = nz - xrr;
        scoef[tid * 5 + 4] = nz - xii;

        const float c  = ich[(size_t)r * 6];
        const float cr = c * isr[(size_t)r * 6];
        const float ci = c * isi[(size_t)r * 6];
        sM1r = cr; sM2r = cr * cr;
        sM1i = ci; sM2i = ci * ci;
    }
    __syncthreads();

    // Each thread streams rows {g, g+2, g+4, g+6} of this block with an
    // explicit register double buffer (7 float4 per row in flight, 2 rows deep).
    const float4* rp = (const float4*)dnn + (size_t)(row0 + g) * (NP / 4) + t;
    const int RSTRIDE = 2 * (NP / 4);       // advance 2 rows per step

    float4 A0, A1, A2, A3, A4, A5, A6;
    float4 B0, B1, B2, B3, B4, B5, B6;

    LOAD7(A, rp);
    LOAD7(B, rp + RSTRIDE);
    COMPUTE7(A, g);
    LOAD7(A, rp + 2 * RSTRIDE);
    COMPUTE7(B, g + 2);
    LOAD7(B, rp + 3 * RSTRIDE);
    COMPUTE7(A, g + 4);
    COMPUTE7(B, g + 6);

    // Block reduction: warp shuffle then across 5 warps via smem
    __shared__ float sred[5 * 8];
    const unsigned FULL = 0xFFFFFFFFu;
    #pragma unroll
    for (int o = 16; o > 0; o >>= 1) {
        sA   += __shfl_down_sync(FULL, sA, o);
        sBr  += __shfl_down_sync(FULL, sBr, o);
        sBi  += __shfl_down_sync(FULL, sBi, o);
        sC   += __shfl_down_sync(FULL, sC, o);
        sM1r += __shfl_down_sync(FULL, sM1r, o);
        sM2r += __shfl_down_sync(FULL, sM2r, o);
        sM1i += __shfl_down_sync(FULL, sM1i, o);
        sM2i += __shfl_down_sync(FULL, sM2i, o);
    }
    const int warp = tid >> 5, lane = tid & 31;
    if (lane == 0) {
        sred[warp * 8 + 0] = sA;   sred[warp * 8 + 1] = sBr;
        sred[warp * 8 + 2] = sBi;  sred[warp * 8 + 3] = sC;
        sred[warp * 8 + 4] = sM1r; sred[warp * 8 + 5] = sM2r;
        sred[warp * 8 + 6] = sM1i; sred[warp * 8 + 7] = sM2i;
    }
    __syncthreads();
    if (tid < 8) {
        float acc = sred[tid] + sred[8 + tid] + sred[16 + tid]
                  + sred[24 + tid] + sred[32 + tid];
        g_partials[blk * 8 + tid] = acc;
    }

    // ---- stage 1: group leader (last of 64 blocks) folds group partials ----
    __shared__ int s_flag;
    __threadfence();
    __syncthreads();
    if (tid == 0)
        s_flag = (atomicAdd(&g_grp_count[grp], 1) == GRPSZ - 1);
    __syncthreads();
    if (!s_flag) return;

    __threadfence();  // acquire: group's partials visible
    if (tid < 8) {
        // fixed-order fp64 sum over the 64 blocks of this group (2-way ILP)
        const int b0 = grp * GRPSZ;
        double e = 0.0, o2 = 0.0;
        #pragma unroll
        for (int k = 0; k < GRPSZ; k += 2) {
            e  += (double)g_partials[(b0 + k)     * 8 + tid];
            o2 += (double)g_partials[(b0 + k + 1) * 8 + tid];
        }
        g_super[grp * 8 + tid] = e + o2;
    }

    // ---- stage 2: final leader (last group done) combines supers ----
    __threadfence();
    __syncthreads();
    if (tid == 0)
        s_flag = (atomicAdd(&g_count, 1) == NGRP - 1);
    __syncthreads();
    if (!s_flag) return;

    __threadfence();  // acquire: all supers visible

    __shared__ double fin[8];
    if (tid < 8) {
        double e = 0.0, o2 = 0.0;
        #pragma unroll 4
        for (int k = 0; k < NGRP; k += 2) {
            e  += g_super[k * 8 + tid];
            o2 += g_super[(k + 1) * 8 + tid];
        }
        fin[tid] = e + o2;
    }
    __syncthreads();
    if (tid == 0) {
        const double invB = 1.0 / (double)BATCH;
        double SumA  = fin[0], SumBr = fin[1], SumBi = fin[2], SumC = fin[3];
        double m1r = fin[4] * invB, m2r = fin[5] * invB;
        double m1i = fin[6] * invB, m2i = fin[7] * invB;
        out[0] = (float)((SumA + 2.0 * m1r * SumBr + 2.0 * m1i * SumBi
                          + (m2r + m2i) * SumC) * invB);
        g_count = 0;                         // self-reset for next graph replay
    }
    if (tid < NGRP) g_grp_count[tid] = 0;    // NGRP=128 < NT=160
}

extern "C" void kernel_launch(void* const* d_in, const int* in_sizes, int n_in,
                              void* d_out, int out_size)
{
    const float* dnn   = (const float*)d_in[0];
    const float* bv    = (const float*)d_in[1];
    const float* hv    = (const float*)d_in[2];
    const float* xr    = (const float*)d_in[3];
    const float* xi    = (const float*)d_in[4];
    const float* isr   = (const float*)d_in[5];
    const float* isi   = (const float*)d_in[6];
    const float* ich   = (const float*)d_in[7];
    const float* noise = (const float*)d_in[8];
    const float* prob  = (const float*)d_in[9];

    isi_fused_kernel<<<NBLK, NT>>>(dnn, bv, hv, xr, xi, isr, isi, ich,
                                   noise, prob, (float*)d_out);
}

// round 17
// speedup vs baseline: 1.2392x; 1.0358x over previous
#include <cuda_runtime.h>
#include <cstdint>

#define BATCH 65536
#define NP 2048
#define CPR 8                       /* rows per chunk */
#define NCHUNK (BATCH / CPR)        /* 8192 */
#define NBLKS 592                   /* 4 per SM on 148-SM parts; single wave */
#define NT 160                      /* 2 groups of 80; 74 active each */
#define INV_SQRT2F 0.70710678118654752440f

// Per-block partial sums: [blk*8 + comp]
// 0..3 : SumA, SumBr, SumBi, SumC   4..7 : sum(c_r), sum(c_r^2), sum(c_i), sum(c_i^2)
__device__ float g_partials[NBLKS * 8];
__device__ int   g_done = 0;

// Stream offsets in float4 units within a row (cols {2,294,586,878,1170,1462,1754}+j,
// j = 4t-2+e  ->  float4 index = {0,73,146,219,292,365,438} + t). Stream 3 is d0.
#define LOAD7(P, rp)                                   \
    {                                                  \
        P##0 = (rp)[0];    P##1 = (rp)[73];            \
        P##2 = (rp)[146];  P##3 = (rp)[219];           \
        P##4 = (rp)[292];  P##5 = (rp)[365];           \
        P##6 = (rp)[438];                              \
    }

#define LANE(P, e, pw)                                                   \
    {                                                                    \
        float S  = (P##0).e + (P##1).e + (P##2).e                        \
                 + (P##4).e + (P##5).e + (P##6).e;                       \
        float ar = fmaf(arc, (P##3).e, brc);                             \
        float ai = fmaf(aic, (P##3).e, bic);                             \
        float bS = bb * S;                                               \
        sA  = fmaf(pw, fmaf(ar, ar, ai * ai), sA);                       \
        sBr = fmaf(pw, ar * bS, sBr);                                    \
        sBi = fmaf(pw, ai * bS, sBi);                                    \
        sC  = fmaf(pw, bS * bS, sC);                                     \
    }

#define COMPUTE7(P, ridx)                                           \
    {                                                               \
        const float bb  = scoef[(ridx) * 5 + 0];                    \
        const float arc = scoef[(ridx) * 5 + 1];                    \
        const float aic = scoef[(ridx) * 5 + 2];                    \
        const float brc = scoef[(ridx) * 5 + 3];                    \
        const float bic = scoef[(ridx) * 5 + 4];                    \
        LANE(P, x, p4.x) LANE(P, y, p4.y)                           \
        LANE(P, z, p4.z) LANE(P, w, p4.w)                           \
    }

__global__ __launch_bounds__(NT, 4) void isi_fused_kernel(
    const float* __restrict__ dnn,
    const float* __restrict__ bv,
    const float* __restrict__ hv,
    const float* __restrict__ xr,
    const float* __restrict__ xi,
    const float* __restrict__ isr,   // ISI_symbols_real (B,6)
    const float* __restrict__ isi,   // ISI_symbols_imag (B,6)
    const float* __restrict__ ich,   // ISI_channels     (B,6)
    const float* __restrict__ noise,
    const float* __restrict__ prob,
    float* __restrict__ out)
{
    const int tid = threadIdx.x;
    const int blk = blockIdx.x;
    const int g   = tid / 80;               // row-parity group 0/1
    const int s   = tid % 80;
    const int t   = (s < 74) ? s : 73;      // clamped float4 j-slot

    __shared__ float scoef[CPR * 5];        // bb, ar_c, ai_c, br_c, bi_c per row

    float sA = 0.f, sBr = 0.f, sBi = 0.f, sC = 0.f;
    float sM1r = 0.f, sM2r = 0.f, sM1i = 0.f, sM2i = 0.f;

    // prob float4 for j = 4t-2 .. 4t+1; zero invalid/inactive lanes.
    float4 p4 = __ldg((const float4*)prob + 219 + t);
    if (s >= 74) { p4.x = 0.f; p4.y = 0.f; p4.z = 0.f; p4.w = 0.f; }
    if (t == 0)  { p4.x = 0.f; p4.y = 0.f; }
    if (t == 73) { p4.z = 0.f; p4.w = 0.f; }

    // ---- persistent chunk loop: chunks {blk, blk+592, ...} ----
    int c = blk;

    // Prologue: chunk-0 coefficients + moments (threads 0..7)
    if (tid < CPR) {
        const int r = c * CPR + tid;
        const float bb  = bv[r];
        const float bh  = bb * hv[r];
        const float xrr = xr[r];
        const float xii = xi[r];
        const float nz  = INV_SQRT2F * noise[r];
        scoef[tid * 5 + 0] = bb;
        scoef[tid * 5 + 1] = bh * xrr;
        scoef[tid * 5 + 2] = bh * xii;
        scoef[tid * 5 + 3] = nz - xrr;
        scoef[tid * 5 + 4] = nz - xii;
        const float cc = ich[(size_t)r * 6];
        const float cr = cc * isr[(size_t)r * 6];
        const float ci = cc * isi[(size_t)r * 6];
        sM1r += cr; sM2r += cr * cr;
        sM1i += ci; sM2i += ci * ci;
    }
    __syncthreads();

    const int RS = 2 * (NP / 4);                       // 2 rows in float4 units
    const size_t CHUNK_STRIDE = (size_t)NBLKS * CPR * (NP / 4);
    const float4* rp = (const float4*)dnn
                     + ((size_t)c * CPR + g) * (NP / 4) + t;

    float4 A0, A1, A2, A3, A4, A5, A6;
    float4 B0, B1, B2, B3, B4, B5, B6;
    LOAD7(A, rp);                                      // row g
    LOAD7(B, rp + RS);                                 // row g+2

    for (;;) {
        const int  cn   = c + NBLKS;
        const bool last = (cn >= NCHUNK);

        // Prefetch next chunk's scalars into registers (latency hidden by
        // this chunk's compute; stored to smem after the barrier below).
        float nb = 0.f, nh = 0.f, nxr = 0.f, nxi = 0.f, nnz = 0.f;
        float ncr = 0.f, nci = 0.f;
        if (tid < CPR && !last) {
            const int r = cn * CPR + tid;
            nb  = bv[r];  nh = hv[r];
            nxr = xr[r];  nxi = xi[r];
            nnz = INV_SQRT2F * noise[r];
            const float cc = ich[(size_t)r * 6];
            ncr = cc * isr[(size_t)r * 6];
            nci = cc * isi[(size_t)r * 6];
        }

        const float4* rpn = rp + CHUNK_STRIDE;

        COMPUTE7(A, g);      LOAD7(A, rp + 2 * RS);    // row g+4
        COMPUTE7(B, g + 2);  LOAD7(B, rp + 3 * RS);    // row g+6
        COMPUTE7(A, g + 4);  if (!last) LOAD7(A, rpn);        // next row g
        COMPUTE7(B, g + 6);  if (!last) LOAD7(B, rpn + RS);   // next row g+2

        __syncthreads();                    // all reads of scoef done
        if (last) break;

        if (tid < CPR) {
            const float bh = nb * nh;
            scoef[tid * 5 + 0] = nb;
            scoef[tid * 5 + 1] = bh * nxr;
            scoef[tid * 5 + 2] = bh * nxi;
            scoef[tid * 5 + 3] = nnz - nxr;
            scoef[tid * 5 + 4] = nnz - nxi;
            sM1r += ncr; sM2r += ncr * ncr;
            sM1i += nci; sM2i += nci * nci;
        }
        __syncthreads();                    // scoef ready for next chunk
        c = cn; rp = rpn;
    }

    // ---- single per-block reduction: warp shuffle, then 5 warps via smem ----
    __shared__ float sred[5 * 8];
    const unsigned FULL = 0xFFFFFFFFu;
    #pragma unroll
    for (int o = 16; o > 0; o >>= 1) {
        sA   += __shfl_down_sync(FULL, sA, o);
        sBr  += __shfl_down_sync(FULL, sBr, o);
        sBi  += __shfl_down_sync(FULL, sBi, o);
        sC   += __shfl_down_sync(FULL, sC, o);
        sM1r += __shfl_down_sync(FULL, sM1r, o);
        sM2r += __shfl_down_sync(FULL, sM2r, o);
        sM1i += __shfl_down_sync(FULL, sM1i, o);
        sM2i += __shfl_down_sync(FULL, sM2i, o);
    }
    const int warp = tid >> 5, lane = tid & 31;
    if (lane == 0) {
        sred[warp * 8 + 0] = sA;   sred[warp * 8 + 1] = sBr;
        sred[warp * 8 + 2] = sBi;  sred[warp * 8 + 3] = sC;
        sred[warp * 8 + 4] = sM1r; sred[warp * 8 + 5] = sM2r;
        sred[warp * 8 + 6] = sM1i; sred[warp * 8 + 7] = sM2i;
    }
    __syncthreads();
    if (tid < 8) {
        float acc = sred[tid] + sred[8 + tid] + sred[16 + tid]
                  + sred[24 + tid] + sred[32 + tid];
        g_partials[blk * 8 + tid] = acc;
    }

    // ---- last-done block folds all partials (fixed order -> deterministic) --
    __shared__ int s_flag;
    __threadfence();
    __syncthreads();
    if (tid == 0)
        s_flag = (atomicAdd(&g_done, 1) == NBLKS - 1);
    __syncthreads();
    if (!s_flag) return;

    __threadfence();                        // acquire: all partials visible

    __shared__ double dsm[64];
    // 64 chains: comp = tid&7, segment = tid>>3 covers 74 blocks each (592=8*74)
    if (tid < 64) {
        const int comp = tid & 7, seg = tid >> 3;
        double acc = 0.0;
        #pragma unroll 4
        for (int k = seg * 74; k < (seg + 1) * 74; ++k)
            acc += (double)g_partials[k * 8 + comp];
        dsm[comp * 8 + seg] = acc;
    }
    __syncthreads();
    if (tid < 8) {
        double sum = 0.0;
        #pragma unroll
        for (int k = 0; k < 8; ++k) sum += dsm[tid * 8 + k];
        dsm[tid] = sum;                     // row tid fully consumed by this thread
    }
    __syncthreads();
    if (tid == 0) {
        const double invB = 1.0 / (double)BATCH;
        double SumA  = dsm[0], SumBr = dsm[1], SumBi = dsm[2], SumC = dsm[3];
        double m1r = dsm[4] * invB, m2r = dsm[5] * invB;
        double m1i = dsm[6] * invB, m2i = dsm[7] * invB;
        out[0] = (float)((SumA + 2.0 * m1r * SumBr + 2.0 * m1i * SumBi
                          + (m2r + m2i) * SumC) * invB);
        g_done = 0;                         // self-reset for next graph replay
    }
}

extern "C" void kernel_launch(void* const* d_in, const int* in_sizes, int n_in,
                              void* d_out, int out_size)
{
    const float* dnn   = (const float*)d_in[0];
    const float* bv    = (const float*)d_in[1];
    const float* hv    = (const float*)d_in[2];
    const float* xr    = (const float*)d_in[3];
    const float* xi    = (const float*)d_in[4];
    const float* isr   = (const float*)d_in[5];
    const float* isi   = (const float*)d_in[6];
    const float* ich   = (const float*)d_in[7];
    const float* noise = (const float*)d_in[8];
    const float* prob  = (const float*)d_in[9];

    isi_fused_kernel<<<NBLKS, NT>>>(dnn, bv, hv, xr, xi, isr, isi, ich,
                                    noise, prob, (float*)d_out);
}